// round 11
// baseline (speedup 1.0000x reference)
#include <cuda_runtime.h>
#include <cstdint>

// Problem constants
#define BATCH      256
#define TREES      64
#define FEAT       16080        // 120*134
#define MASK_W     1000
#define K_TOP      200
#define ROW_F4     (FEAT / 4)   // 4020
#define LIVE_F4    (MASK_W / 4) // 250  (columns [0,1000) hold all nonzeros)
#define NROWS      (BATCH * TREES)   // 16384 rv rows

// ---------------------------------------------------------------------------
// Kernel A: block-per-tree exact top-200 via __syncthreads_count binary search,
//   PLUS zeroing of its own attention row's tail (columns [1000,16080)).
//   Triggers programmatic launch completion at entry so the store kernel's
//   grid launches immediately and overlaps this one (64 blocks => all wave-1
//   resident => all triggers fire instantly).
// ---------------------------------------------------------------------------
__global__ __launch_bounds__(1024)
void topk_kernel(const float* __restrict__ mask, float* __restrict__ att_out)
{
    cudaTriggerProgrammaticLaunchCompletion();

    const int t   = blockIdx.x;
    const int tid = threadIdx.x;
    float* att_row = att_out + (size_t)t * FEAT;

    __shared__ unsigned int skey[1024];

    // Load + order-preserving float->uint transform
    float v = 0.0f;
    unsigned int key = 0u;
    if (tid < MASK_W) {
        v = mask[t * MASK_W + tid];
        const int s = __float_as_int(v);
        key = (s < 0) ? ~(unsigned int)s : ((unsigned int)s | 0x80000000u);
    }
    skey[tid] = key;   // consumed only on the rare tie path; the search-loop
                       // barriers below order this write before any read

    // Zero this attention row's tail now — independent of the search, so the
    // stores overlap the barrier-bound binary search below.
    {
        float4 z; z.x = 0.f; z.y = 0.f; z.z = 0.f; z.w = 0.f;
        float4* row4 = reinterpret_cast<float4*>(att_row);
        for (int f4 = LIVE_F4 + tid; f4 < ROW_F4; f4 += 1024) row4[f4] = z;
    }

    // Binary search: thr = max T with count(key >= T) >= K_TOP (200th largest).
    // Sentinel key 0 (tid >= 1000) is never counted: midpoints are >= 1 and
    // finite-float keys are > 0.
    unsigned int lo = 0u, hi = 0xFFFFFFFFu;
    while (lo < hi) {
        const unsigned int mid = lo + ((hi - lo) >> 1) + 1u;   // upper mid
        const int total = __syncthreads_count(key >= mid);
        if (total >= K_TOP) lo = mid; else hi = mid - 1u;
    }
    const unsigned int thr = lo;

    // Strictly-greater / equal counts (block-uniform results)
    const int cgt = __syncthreads_count(key > thr);
    const int ceq = __syncthreads_count(key == thr);
    const int need = K_TOP - cgt;            // equals to accept (1 <= need <= ceq)

    bool sel = (key > thr);
    if (key == thr) {
        if (need >= ceq) {
            sel = true;                      // all ties fit (common case)
        } else {                             // boundary tie: lowest indices win
            int r = 0;
            for (int j = 0; j < tid; ++j) r += (skey[j] == thr);
            sel = (r < need);
        }
    }

    if (tid < MASK_W) {
        att_row[tid] = sel ? (1.0f / (1.0f + expf(-v))) : 0.0f;
    }
}

// ---------------------------------------------------------------------------
// Kernel B: return_value store stream, 4 independent float4 stores per thread.
//   grid = (4, 16384), block = 256. base = bx*256+tid in [0,1024); thread
//   stores columns {base, base+1024, base+2048, base+3072} of its row
//   (+3072 predicated off for base >= 948 since ROW_F4 = 4020).
//   Only bx==0 blocks touch attention: they do a block-uniform
//   cudaGridDependencySynchronize(), then multiply x*att for tid < 250.
//   The other 75% of blocks stream zero stores with no dependency code.
// ---------------------------------------------------------------------------
__global__ __launch_bounds__(256)
void rv_kernel(const float* __restrict__ x,
               const float* __restrict__ att,
               float*       __restrict__ out)
{
    const int tid  = threadIdx.x;
    const int base = blockIdx.x * 256 + tid;                 // 0 .. 1023
    const int row  = blockIdx.y;                             // b*TREES + t

    float4* dst = reinterpret_cast<float4*>(out + (size_t)row * FEAT);
    float4 z; z.x = 0.f; z.y = 0.f; z.z = 0.f; z.w = 0.f;

    float4 r = z;
    if (blockIdx.x == 0) {
        // Block-uniform wait for topk_kernel's attention writes.
        cudaGridDependencySynchronize();
        if (tid < LIVE_F4) {
            const int t = row & (TREES - 1);
            const int b = row >> 6;
            const float4 xa = reinterpret_cast<const float4*>(x   + (size_t)b * FEAT)[tid];
            const float4 aa = reinterpret_cast<const float4*>(att + (size_t)t * FEAT)[tid];
            r.x = xa.x * aa.x;
            r.y = xa.y * aa.y;
            r.z = xa.z * aa.z;
            r.w = xa.w * aa.w;
        }
    }
    dst[base]        = r;
    dst[base + 1024] = z;
    dst[base + 2048] = z;
    if (base + 3072 < ROW_F4) dst[base + 3072] = z;
}

// ---------------------------------------------------------------------------
// Launch: topk (writes full attention rows), then rv with programmatic
// stream serialization (PDL) so rv's grid launches while topk is in flight.
// ---------------------------------------------------------------------------
extern "C" void kernel_launch(void* const* d_in, const int* in_sizes, int n_in,
                              void* d_out, int out_size)
{
    const float* x    = (const float*)d_in[0];   // (256, 120, 134) fp32
    const float* mask = (const float*)d_in[1];   // (64, 1000) fp32

    float* out = (float*)d_out;
    float* att_out = out + (size_t)NROWS * FEAT; // (64, 16080) appended

    // A) per-tree top-200 + attention row (live values + zero tail)
    topk_kernel<<<TREES, 1024>>>(mask, att_out);

    // B) return_value store stream, PDL-overlapped with A
    cudaLaunchConfig_t cfg = {};
    cfg.gridDim  = dim3(4, NROWS, 1);
    cfg.blockDim = dim3(256, 1, 1);
    cfg.dynamicSmemBytes = 0;
    cudaLaunchAttribute attr[1];
    attr[0].id = cudaLaunchAttributeProgrammaticStreamSerialization;
    attr[0].val.programmaticStreamSerializationAllowed = 1;
    cfg.attrs = attr;
    cfg.numAttrs = 1;
    cudaLaunchKernelEx(&cfg, rv_kernel, x, (const float*)att_out, out);
}